// round 9
// baseline (speedup 1.0000x reference)
#include <cuda_runtime.h>
#include <math.h>
#include <stdint.h>

// ---------------- problem constants ----------------
#define B_     8
#define CIN    64
#define COUT   128
#define HW     4096            // 64*64
#define LSEQ   4096
#define BL     32768           // B_*LSEQ
#define DI     256             // D_INNER
#define DS     64              // D_STATE
#define DTR    8
#define DBLN   136             // DTR + 2*DS

// ---------------- scratch (static device globals; no allocation) ----------------
__device__ float g_tin[BL * 64];       // x transposed   (BL,64)
__device__ float g_t0 [BL * 128];      // after proj_in  (BL,128)
__device__ float g_xz [BL * 512];      // in_proj out    (BL,512)
__device__ float g_xs [BL * 256];      // conv1d+silu    (BL,256)
__device__ float g_dbl[BL * 136];      // x_proj out     (BL,136)
__device__ float g_dt [BL * 256];      // softplus dt    (BL,256)
__device__ float g_y  [BL * 256];      // scan out fused (BL,256)
__device__ float g_t1 [BL * 128];      // out_proj       (BL,128)
__device__ float g_t2 [BL * 128];      // proj_out+LN    (BL,128)
__device__ float g_f  [B_ * 128 * HW]; // NCHW feature
__device__ float g_st [1024 * 2];      // instnorm stats

__device__ __forceinline__ float siluf(float v) { return v / (1.f + __expf(-v)); }

// ---------------- batched 32x32 tile transpose ----------------
// per batch: in (R,C) row-major -> out (C,R) row-major
__global__ void ktranspose(const float* __restrict__ in, float* __restrict__ out,
                           int R, int C) {
    __shared__ float s[32][33];
    size_t boff = (size_t)blockIdx.z * R * C;
    in += boff; out += boff;
    int c0 = blockIdx.x * 32, r0 = blockIdx.y * 32;
    for (int j = threadIdx.y; j < 32; j += blockDim.y) {
        int r = r0 + j, c = c0 + threadIdx.x;
        s[j][threadIdx.x] = (r < R && c < C) ? in[(size_t)r * C + c] : 0.f;
    }
    __syncthreads();
    for (int j = threadIdx.y; j < 32; j += blockDim.y) {
        int c = c0 + j, r = r0 + threadIdx.x;
        if (c < C && r < R) out[(size_t)c * R + r] = s[threadIdx.x][j];
    }
}

// ---------------- generic SGEMM:  C[m,n] = sum_k A[m,k] * W[n,k]  ----------------
// ACT: 0 none, 1 silu.  AMODE: 0 plain A (lda), 1 implicit-gemm conv3x3 gather from NCHW.
// CMODE: 0 row-major C (ldc), 1 scatter to NCHW (m=b*4096+hw, n=cout).
template<int ACT, int AMODE, int CMODE>
__global__ void kgemm(const float* __restrict__ A, const float* __restrict__ W,
                      const float* __restrict__ bias, float* __restrict__ C,
                      int M, int N, int K, int lda, int ldc) {
    __shared__ __align__(16) float As[64][17];
    __shared__ __align__(16) float Ws[16][68];

    int m0 = blockIdx.y * 64, n0 = blockIdx.x * 64;
    int tx = threadIdx.x & 15, ty = threadIdx.x >> 4;
    float acc[4][4];
#pragma unroll
    for (int i = 0; i < 4; i++)
#pragma unroll
        for (int j = 0; j < 4; j++) acc[i][j] = 0.f;

    for (int k0 = 0; k0 < K; k0 += 16) {
        // --- A tile ---
#pragma unroll
        for (int p = 0; p < 4; p++) {
            int pos = threadIdx.x + p * 256;
            int row = pos >> 4, col = pos & 15;
            float v;
            if (AMODE == 0) {
                v = A[(size_t)(m0 + row) * lda + (k0 + col)];
            } else {
                int k = k0 + col;
                int cin = (k * 7282) >> 16;       // k/9 for k<1152
                int tap = k - cin * 9;
                int kh = (tap >= 6) ? 2 : (tap >= 3 ? 1 : 0);
                int kw = tap - kh * 3;
                int m  = m0 + row;
                int b  = m >> 12;
                int hw = m & 4095;
                int h  = (hw >> 6) + kh - 1;
                int w  = (hw & 63) + kw - 1;
                v = 0.f;
                if ((unsigned)h < 64u && (unsigned)w < 64u)
                    v = A[(((size_t)b * 128 + cin) << 12) + (h << 6) + w];
            }
            As[row][col] = v;
        }
        // --- W tile (transposed into Ws[k][n]) ---
#pragma unroll
        for (int p = 0; p < 4; p++) {
            int pos = threadIdx.x + p * 256;
            int row = pos >> 4, col = pos & 15;     // row: n-offset, col: k-offset
            int n = n0 + row;
            Ws[col][row] = (n < N) ? W[(size_t)n * K + (k0 + col)] : 0.f;
        }
        __syncthreads();
#pragma unroll
        for (int kk = 0; kk < 16; kk++) {
            float a[4];
#pragma unroll
            for (int i = 0; i < 4; i++) a[i] = As[ty * 4 + i][kk];
            float4 bv = *(const float4*)&Ws[kk][tx * 4];
            float bb[4] = {bv.x, bv.y, bv.z, bv.w};
#pragma unroll
            for (int i = 0; i < 4; i++)
#pragma unroll
                for (int j = 0; j < 4; j++) acc[i][j] += a[i] * bb[j];
        }
        __syncthreads();
    }
#pragma unroll
    for (int i = 0; i < 4; i++) {
        int m = m0 + ty * 4 + i;
#pragma unroll
        for (int j = 0; j < 4; j++) {
            int n = n0 + tx * 4 + j;
            if (n < N) {
                float v = acc[i][j] + (bias ? bias[n] : 0.f);
                if (ACT == 1) v = siluf(v);
                if (CMODE == 0) C[(size_t)m * ldc + n] = v;
                else {
                    int b = m >> 12, hw = m & 4095;
                    C[(((size_t)b * 128 + n) << 12) + hw] = v;
                }
            }
        }
    }
}

// ---------------- causal depthwise conv1d (k=4) + silu ----------------
// reads xm = xz[:, 0:256] (row stride 512), writes xs (BL,256)
__global__ void kconv1d(const float* __restrict__ xz, const float* __restrict__ w,
                        const float* __restrict__ b, float* __restrict__ xs) {
    int d = threadIdx.x;          // 0..255
    int m = blockIdx.x;           // 0..32767
    int l = m & 4095;
    float acc = b[d];
#pragma unroll
    for (int k = 0; k < 4; k++) {
        int ll = l + k - 3;
        if (ll >= 0) acc += w[d * 4 + k] * xz[(size_t)(m + k - 3) * 512 + d];
    }
    xs[(size_t)m * 256 + d] = siluf(acc);
}

// ---------------- dt projection + softplus ----------------
__global__ void kdt(const float* __restrict__ dbl, const float* __restrict__ wt,
                    const float* __restrict__ bt, float* __restrict__ dt) {
    int d = threadIdx.x;          // 256
    int m = blockIdx.x;           // 32768
    __shared__ float s[8];
    if (d < 8) s[d] = dbl[(size_t)m * 136 + d];
    __syncthreads();
    float acc = bt[d];
#pragma unroll
    for (int r = 0; r < 8; r++) acc += s[r] * wt[d * 8 + r];
    float sp = fmaxf(acc, 0.f) + log1pf(__expf(-fabsf(acc)));
    dt[(size_t)m * 256 + d] = sp;
}

// ---------------- selective scan (warp per (b,d), 2 states/lane) + fused gate ----------------
__global__ void kscan(const float* __restrict__ dt, const float* __restrict__ xs,
                      const float* __restrict__ dbl, const float* __restrict__ xz,
                      const float* __restrict__ A_log, const float* __restrict__ Dv,
                      float* __restrict__ y) {
    int gw   = (blockIdx.x * blockDim.x + threadIdx.x) >> 5;
    int lane = threadIdx.x & 31;
    int b = gw >> 8;          // batch
    int d = gw & 255;         // channel
    float a1 = -__expf(A_log[d * 64 + 2 * lane]);
    float a2 = -__expf(A_log[d * 64 + 2 * lane + 1]);
    float Dd = Dv[d];
    float h1 = 0.f, h2 = 0.f;
    size_t m = (size_t)b * 4096;
    const float* pdt = dt  + m * 256 + d;
    const float* pu  = xs  + m * 256 + d;
    const float* pz  = xz  + m * 512 + 256 + d;
    const float* pb  = dbl + m * 136 + 8  + 2 * lane;
    const float* pc  = dbl + m * 136 + 72 + 2 * lane;
    float* py = y + m * 256 + d;

    float dtv = *pdt, u = *pu, zv = *pz;
    float2 bc = *(const float2*)pb, cc = *(const float2*)pc;
    for (int l = 0; l < 4096; l++) {
        float dt0 = dtv, u0 = u, z0 = zv;
        float2 b0 = bc, c0 = cc;
        if (l < 4095) {       // prefetch next step
            pdt += 256; pu += 256; pz += 512; pb += 136; pc += 136;
            dtv = *pdt; u = *pu; zv = *pz;
            bc = *(const float2*)pb; cc = *(const float2*)pc;
        }
        float dA1 = __expf(dt0 * a1);
        float dA2 = __expf(dt0 * a2);
        float cu  = dt0 * u0;
        h1 = h1 * dA1 + cu * b0.x;
        h2 = h2 * dA2 + cu * b0.y;
        float yp = h1 * c0.x + h2 * c0.y;
#pragma unroll
        for (int o = 16; o; o >>= 1) yp += __shfl_xor_sync(0xffffffffu, yp, o);
        if (lane == 0) *py = (yp + u0 * Dd) * siluf(z0);
        py += 256;
    }
}

// ---------------- LayerNorm over last dim (128), in place ----------------
__global__ void kln(float* __restrict__ t, const float* __restrict__ g,
                    const float* __restrict__ bb) {
    int m = blockIdx.x, c = threadIdx.x;           // 128 threads
    float v = t[(size_t)m * 128 + c];
    float s = v, q = v * v;
    int lane = c & 31, wid = c >> 5;
#pragma unroll
    for (int o = 16; o; o >>= 1) {
        s += __shfl_xor_sync(0xffffffffu, s, o);
        q += __shfl_xor_sync(0xffffffffu, q, o);
    }
    __shared__ float ss[4], sq[4], smv[2];
    if (lane == 0) { ss[wid] = s; sq[wid] = q; }
    __syncthreads();
    if (c == 0) {
        float S = 0.f, Q = 0.f;
        for (int i = 0; i < 4; i++) { S += ss[i]; Q += sq[i]; }
        float mu = S * (1.f / 128.f);
        float var = Q * (1.f / 128.f) - mu * mu;
        smv[0] = mu; smv[1] = rsqrtf(var + 1e-5f);
    }
    __syncthreads();
    t[(size_t)m * 128 + c] = (v - smv[0]) * smv[1] * g[c] + bb[c];
}

// ---------------- instance-norm stats over HW per (b,c) ----------------
__global__ void kistats(const float* __restrict__ f, float* __restrict__ st) {
    int bc = blockIdx.x;                             // 1024
    const float* p = f + (size_t)bc * 4096;
    float s = 0.f, q = 0.f;
    for (int i = threadIdx.x; i < 4096; i += 256) { float v = p[i]; s += v; q += v * v; }
    int lane = threadIdx.x & 31, wid = threadIdx.x >> 5;
#pragma unroll
    for (int o = 16; o; o >>= 1) {
        s += __shfl_xor_sync(0xffffffffu, s, o);
        q += __shfl_xor_sync(0xffffffffu, q, o);
    }
    __shared__ float ss[8], sq[8];
    if (lane == 0) { ss[wid] = s; sq[wid] = q; }
    __syncthreads();
    if (threadIdx.x == 0) {
        float S = 0.f, Q = 0.f;
        for (int i = 0; i < 8; i++) { S += ss[i]; Q += sq[i]; }
        float mu = S * (1.f / 4096.f);
        float var = Q * (1.f / 4096.f) - mu * mu;
        st[bc * 2] = mu; st[bc * 2 + 1] = rsqrtf(var + 1e-5f);
    }
}

// ---------------- instance-norm apply + leaky relu, in place ----------------
__global__ void kiapply(float* __restrict__ f, const float* __restrict__ st,
                        const float* __restrict__ g, const float* __restrict__ b) {
    size_t i = (size_t)blockIdx.x * 256 + threadIdx.x;
    int bc = (int)(i >> 12);
    int c  = bc & 127;
    float v = f[i];
    v = (v - st[bc * 2]) * st[bc * 2 + 1] * g[c] + b[c];
    f[i] = v >= 0.f ? v : 0.01f * v;
}

// ---------------- launch ----------------
extern "C" void kernel_launch(void* const* d_in, const int* in_sizes, int n_in,
                              void* d_out, int out_size) {
    const float* x          = (const float*)d_in[0];
    const float* proj_in_w  = (const float*)d_in[1];
    const float* proj_in_b  = (const float*)d_in[2];
    const float* in_proj_w  = (const float*)d_in[3];
    const float* conv1d_w   = (const float*)d_in[4];
    const float* conv1d_b   = (const float*)d_in[5];
    const float* x_proj_w   = (const float*)d_in[6];
    const float* dt_proj_w  = (const float*)d_in[7];
    const float* dt_proj_b  = (const float*)d_in[8];
    const float* A_log      = (const float*)d_in[9];
    const float* Dv         = (const float*)d_in[10];
    const float* out_proj_w = (const float*)d_in[11];
    const float* proj_out_w = (const float*)d_in[12];
    const float* proj_out_b = (const float*)d_in[13];
    const float* ln_g       = (const float*)d_in[14];
    const float* ln_b       = (const float*)d_in[15];
    const float* in_g       = (const float*)d_in[16];
    const float* in_b       = (const float*)d_in[17];
    const float* conv2d_w   = (const float*)d_in[18];
    const float* conv2d_b   = (const float*)d_in[19];

    float *tin, *t0, *xz, *xs, *dbl, *dt, *y, *t1, *t2, *f, *st;
    cudaGetSymbolAddress((void**)&tin, g_tin);
    cudaGetSymbolAddress((void**)&t0,  g_t0);
    cudaGetSymbolAddress((void**)&xz,  g_xz);
    cudaGetSymbolAddress((void**)&xs,  g_xs);
    cudaGetSymbolAddress((void**)&dbl, g_dbl);
    cudaGetSymbolAddress((void**)&dt,  g_dt);
    cudaGetSymbolAddress((void**)&y,   g_y);
    cudaGetSymbolAddress((void**)&t1,  g_t1);
    cudaGetSymbolAddress((void**)&t2,  g_t2);
    cudaGetSymbolAddress((void**)&f,   g_f);
    cudaGetSymbolAddress((void**)&st,  g_st);

    dim3 tb(32, 8);
    // 1) x (B,64,L) -> tin (B*L,64)
    ktranspose<<<dim3(128, 2, 8), tb>>>(x, tin, 64, 4096);
    // 2) t0 = silu(tin @ proj_in_w^T + b)   (BL,128)
    kgemm<1, 0, 0><<<dim3(2, 512), 256>>>(tin, proj_in_w, proj_in_b, t0,
                                          BL, 128, 64, 64, 128);
    // 3) xz = t0 @ in_proj_w^T              (BL,512)
    kgemm<0, 0, 0><<<dim3(8, 512), 256>>>(t0, in_proj_w, nullptr, xz,
                                          BL, 512, 128, 128, 512);
    // 4) xs = silu(causal conv1d(xm))       (BL,256)
    kconv1d<<<BL, 256>>>(xz, conv1d_w, conv1d_b, xs);
    // 5) dbl = xs @ x_proj_w^T              (BL,136)
    kgemm<0, 0, 0><<<dim3(3, 512), 256>>>(xs, x_proj_w, nullptr, dbl,
                                          BL, 136, 256, 256, 136);
    // 6) dt = softplus(dbl[:,:8] @ dt_proj_w^T + b)  (BL,256)
    kdt<<<BL, 256>>>(dbl, dt_proj_w, dt_proj_b, dt);
    // 7) selective scan + residual D + silu(z) gate  (BL,256)
    kscan<<<256, 256>>>(dt, xs, dbl, xz, A_log, Dv, y);
    // 8) t1 = y @ out_proj_w^T              (BL,128)
    kgemm<0, 0, 0><<<dim3(2, 512), 256>>>(y, out_proj_w, nullptr, t1,
                                          BL, 128, 256, 256, 128);
    // 9) t2 = t1 @ proj_out_w^T + b         (BL,128)
    kgemm<0, 0, 0><<<dim3(2, 512), 256>>>(t1, proj_out_w, proj_out_b, t2,
                                          BL, 128, 128, 128, 128);
    // 10) LayerNorm over 128, in place
    kln<<<BL, 128>>>(t2, ln_g, ln_b);
    // 11) t2 (B,L,128) -> f (B,128,L)
    ktranspose<<<dim3(4, 128, 8), tb>>>(t2, f, 4096, 128);
    // 12-13) instance norm + leaky relu, in place
    kistats<<<1024, 256>>>(f, st);
    kiapply<<<16384, 256>>>(f, st, in_g, in_b);
    // 14) conv2d 3x3 SAME as implicit GEMM (K=1152) + bias -> d_out (NCHW)
    kgemm<0, 1, 1><<<dim3(2, 512), 256>>>(f, conv2d_w, conv2d_b, (float*)d_out,
                                          BL, 128, 1152, 0, 0);
}

// round 12
// speedup vs baseline: 1.0499x; 1.0499x over previous
#include <cuda_runtime.h>
#include <math.h>
#include <stdint.h>

// ---------------- problem constants ----------------
#define B_     8
#define CIN    64
#define COUT   128
#define HW     4096            // 64*64
#define LSEQ   4096
#define BL     32768           // B_*LSEQ
#define DI     256             // D_INNER
#define DS     64              // D_STATE
#define DTR    8
#define DBLN   136             // DTR + 2*DS

// ---------------- scratch (static device globals; no allocation) ----------------
__device__ float g_tin[BL * 64];       // x transposed   (BL,64)
__device__ float g_t0 [BL * 128];      // after proj_in  (BL,128)
__device__ float g_xz [BL * 512];      // in_proj out    (BL,512)
__device__ float g_xs [BL * 256];      // conv1d+silu    (BL,256)
__device__ float g_dbl[BL * 136];      // x_proj out     (BL,136)
__device__ float g_dt [BL * 256];      // softplus dt    (BL,256)
__device__ float g_y  [BL * 256];      // scan out fused (BL,256)
__device__ float g_t1 [BL * 128];      // out_proj       (BL,128)
__device__ float g_t2 [BL * 128];      // proj_out+LN    (BL,128)
__device__ float g_f  [B_ * 128 * HW]; // NCHW feature
__device__ float g_st [1024 * 2];      // instnorm stats

__device__ __forceinline__ float siluf(float v) { return v / (1.f + __expf(-v)); }

// ---------------- batched 32x32 tile transpose ----------------
__global__ void ktranspose(const float* __restrict__ in, float* __restrict__ out,
                           int R, int C) {
    __shared__ float s[32][33];
    size_t boff = (size_t)blockIdx.z * R * C;
    in += boff; out += boff;
    int c0 = blockIdx.x * 32, r0 = blockIdx.y * 32;
    for (int j = threadIdx.y; j < 32; j += blockDim.y) {
        int r = r0 + j, c = c0 + threadIdx.x;
        s[j][threadIdx.x] = (r < R && c < C) ? in[(size_t)r * C + c] : 0.f;
    }
    __syncthreads();
    for (int j = threadIdx.y; j < 32; j += blockDim.y) {
        int c = c0 + j, r = r0 + threadIdx.x;
        if (c < C && r < R) out[(size_t)c * R + r] = s[threadIdx.x][j];
    }
}

// ---------------- SGEMM v2: 128x64 tile, 8x4 micro, k-major A staging ----------------
// C[m,n] = sum_k A[m,k] * W[n,k]
// ACT: 0 none, 1 silu.  AMODE: 0 plain A (lda), 1 implicit-gemm conv3x3 gather from NCHW.
// CMODE: 0 row-major C (ldc, float4 stores), 1 scatter to NCHW.
// Requirements: M % 128 == 0, K % 16 == 0, N % 4 == 0, ldc % 4 == 0.
template<int ACT, int AMODE, int CMODE>
__global__ void kgemm(const float* __restrict__ A, const float* __restrict__ W,
                      const float* __restrict__ bias, float* __restrict__ C,
                      int M, int N, int K, int lda, int ldc) {
    __shared__ __align__(16) float Ast[16][132];   // [k][m], pad 4
    __shared__ __align__(16) float Wst[16][68];    // [k][n], pad 4

    int m0 = blockIdx.y * 128, n0 = blockIdx.x * 64;
    int tid = threadIdx.x;
    int tx = tid & 15, ty = tid >> 4;              // tx: n-group(4), ty: m-group(8)
    float acc[8][4];
#pragma unroll
    for (int i = 0; i < 8; i++)
#pragma unroll
        for (int j = 0; j < 4; j++) acc[i][j] = 0.f;

    for (int k0 = 0; k0 < K; k0 += 16) {
        // --- A tile: 128 m-rows x 16 k, stored transposed into Ast[k][m] ---
#pragma unroll
        for (int p = 0; p < 8; p++) {
            int pos = tid + p * 256;
            int row = pos >> 4, col = pos & 15;    // row: m-off, col: k-off
            float v;
            if (AMODE == 0) {
                v = A[(size_t)(m0 + row) * lda + (k0 + col)];
            } else {
                int k   = k0 + col;
                int cin = (k * 7282) >> 16;        // k/9 for k<1152
                int tap = k - cin * 9;
                int kh  = (tap >= 6) ? 2 : (tap >= 3 ? 1 : 0);
                int kw  = tap - kh * 3;
                int m   = m0 + row;
                int b   = m >> 12;
                int hw  = m & 4095;
                int h   = (hw >> 6) + kh - 1;
                int w   = (hw & 63) + kw - 1;
                v = 0.f;
                if ((unsigned)h < 64u && (unsigned)w < 64u)
                    v = A[(((size_t)b * 128 + cin) << 12) + (h << 6) + w];
            }
            Ast[col][row] = v;
        }
        // --- W tile: 64 n-rows x 16 k, stored transposed into Wst[k][n] ---
#pragma unroll
        for (int p = 0; p < 4; p++) {
            int pos = tid + p * 256;
            int row = pos >> 4, col = pos & 15;    // row: n-off, col: k-off
            int n = n0 + row;
            Wst[col][row] = (n < N) ? W[(size_t)n * K + (k0 + col)] : 0.f;
        }
        __syncthreads();
#pragma unroll
        for (int kk = 0; kk < 16; kk++) {
            float4 a0 = *(const float4*)&Ast[kk][ty * 8];
            float4 a1 = *(const float4*)&Ast[kk][ty * 8 + 4];
            float4 bv = *(const float4*)&Wst[kk][tx * 4];
            float av[8] = {a0.x, a0.y, a0.z, a0.w, a1.x, a1.y, a1.z, a1.w};
            float bb[4] = {bv.x, bv.y, bv.z, bv.w};
#pragma unroll
            for (int i = 0; i < 8; i++)
#pragma unroll
                for (int j = 0; j < 4; j++) acc[i][j] += av[i] * bb[j];
        }
        __syncthreads();
    }

    int nbase = n0 + tx * 4;
    float bz[4] = {0.f, 0.f, 0.f, 0.f};
    if (bias && nbase < N) {
#pragma unroll
        for (int j = 0; j < 4; j++) bz[j] = bias[nbase + j];
    }
#pragma unroll
    for (int i = 0; i < 8; i++) {
        int m = m0 + ty * 8 + i;
        if (nbase < N) {
            float4 o;
            o.x = acc[i][0] + bz[0];
            o.y = acc[i][1] + bz[1];
            o.z = acc[i][2] + bz[2];
            o.w = acc[i][3] + bz[3];
            if (ACT == 1) { o.x = siluf(o.x); o.y = siluf(o.y); o.z = siluf(o.z); o.w = siluf(o.w); }
            if (CMODE == 0) {
                *(float4*)&C[(size_t)m * ldc + nbase] = o;
            } else {
                int b = m >> 12, hw = m & 4095;
                float oo[4] = {o.x, o.y, o.z, o.w};
#pragma unroll
                for (int j = 0; j < 4; j++)
                    C[(((size_t)b * 128 + (nbase + j)) << 12) + hw] = oo[j];
            }
        }
    }
}

// ---------------- causal depthwise conv1d (k=4) + silu ----------------
__global__ void kconv1d(const float* __restrict__ xz, const float* __restrict__ w,
                        const float* __restrict__ b, float* __restrict__ xs) {
    int d = threadIdx.x;          // 0..255
    int m = blockIdx.x;           // 0..32767
    int l = m & 4095;
    float acc = b[d];
#pragma unroll
    for (int k = 0; k < 4; k++) {
        int ll = l + k - 3;
        if (ll >= 0) acc += w[d * 4 + k] * xz[(size_t)(m + k - 3) * 512 + d];
    }
    xs[(size_t)m * 256 + d] = siluf(acc);
}

// ---------------- dt projection + softplus ----------------
__global__ void kdt(const float* __restrict__ dbl, const float* __restrict__ wt,
                    const float* __restrict__ bt, float* __restrict__ dt) {
    int d = threadIdx.x;          // 256
    int m = blockIdx.x;           // 32768
    __shared__ float s[8];
    if (d < 8) s[d] = dbl[(size_t)m * 136 + d];
    __syncthreads();
    float acc = bt[d];
#pragma unroll
    for (int r = 0; r < 8; r++) acc += s[r] * wt[d * 8 + r];
    float sp = fmaxf(acc, 0.f) + log1pf(__expf(-fabsf(acc)));
    dt[(size_t)m * 256 + d] = sp;
}

// ---------------- selective scan (warp per (b,d), 2 states/lane) + fused gate ----------------
__global__ void kscan(const float* __restrict__ dt, const float* __restrict__ xs,
                      const float* __restrict__ dbl, const float* __restrict__ xz,
                      const float* __restrict__ A_log, const float* __restrict__ Dv,
                      float* __restrict__ y) {
    int gw   = (blockIdx.x * blockDim.x + threadIdx.x) >> 5;
    int lane = threadIdx.x & 31;
    int b = gw >> 8;          // batch
    int d = gw & 255;         // channel
    float a1 = -__expf(A_log[d * 64 + 2 * lane]);
    float a2 = -__expf(A_log[d * 64 + 2 * lane + 1]);
    float Dd = Dv[d];
    float h1 = 0.f, h2 = 0.f;
    size_t m = (size_t)b * 4096;
    const float* pdt = dt  + m * 256 + d;
    const float* pu  = xs  + m * 256 + d;
    const float* pz  = xz  + m * 512 + 256 + d;
    const float* pb  = dbl + m * 136 + 8  + 2 * lane;
    const float* pc  = dbl + m * 136 + 72 + 2 * lane;
    float* py = y + m * 256 + d;

    float dtv = *pdt, u = *pu, zv = *pz;
    float2 bc = *(const float2*)pb, cc = *(const float2*)pc;
    for (int l = 0; l < 4096; l++) {
        float dt0 = dtv, u0 = u, z0 = zv;
        float2 b0 = bc, c0 = cc;
        if (l < 4095) {       // prefetch next step
            pdt += 256; pu += 256; pz += 512; pb += 136; pc += 136;
            dtv = *pdt; u = *pu; zv = *pz;
            bc = *(const float2*)pb; cc = *(const float2*)pc;
        }
        float dA1 = __expf(dt0 * a1);
        float dA2 = __expf(dt0 * a2);
        float cu  = dt0 * u0;
        h1 = h1 * dA1 + cu * b0.x;
        h2 = h2 * dA2 + cu * b0.y;
        float yp = h1 * c0.x + h2 * c0.y;
#pragma unroll
        for (int o = 16; o; o >>= 1) yp += __shfl_xor_sync(0xffffffffu, yp, o);
        if (lane == 0) *py = (yp + u0 * Dd) * siluf(z0);
        py += 256;
    }
}

// ---------------- LayerNorm over last dim (128), in place ----------------
__global__ void kln(float* __restrict__ t, const float* __restrict__ g,
                    const float* __restrict__ bb) {
    int m = blockIdx.x, c = threadIdx.x;           // 128 threads
    float v = t[(size_t)m * 128 + c];
    float s = v, q = v * v;
    int lane = c & 31, wid = c >> 5;
#pragma unroll
    for (int o = 16; o; o >>= 1) {
        s += __shfl_xor_sync(0xffffffffu, s, o);
        q += __shfl_xor_sync(0xffffffffu, q, o);
    }
    __shared__ float ss[4], sq[4], smv[2];
    if (lane == 0) { ss[wid] = s; sq[wid] = q; }
    __syncthreads();
    if (c == 0) {
        float S = 0.f, Q = 0.f;
        for (int i = 0; i < 4; i++) { S += ss[i]; Q += sq[i]; }
        float mu = S * (1.f / 128.f);
        float var = Q * (1.f / 128.f) - mu * mu;
        smv[0] = mu; smv[1] = rsqrtf(var + 1e-5f);
    }
    __syncthreads();
    t[(size_t)m * 128 + c] = (v - smv[0]) * smv[1] * g[c] + bb[c];
}

// ---------------- instance-norm stats over HW per (b,c) ----------------
__global__ void kistats(const float* __restrict__ f, float* __restrict__ st) {
    int bc = blockIdx.x;                             // 1024
    const float* p = f + (size_t)bc * 4096;
    float s = 0.f, q = 0.f;
    for (int i = threadIdx.x; i < 4096; i += 256) { float v = p[i]; s += v; q += v * v; }
    int lane = threadIdx.x & 31, wid = threadIdx.x >> 5;
#pragma unroll
    for (int o = 16; o; o >>= 1) {
        s += __shfl_xor_sync(0xffffffffu, s, o);
        q += __shfl_xor_sync(0xffffffffu, q, o);
    }
    __shared__ float ss[8], sq[8];
    if (lane == 0) { ss[wid] = s; sq[wid] = q; }
    __syncthreads();
    if (threadIdx.x == 0) {
        float S = 0.f, Q = 0.f;
        for (int i = 0; i < 8; i++) { S += ss[i]; Q += sq[i]; }
        float mu = S * (1.f / 4096.f);
        float var = Q * (1.f / 4096.f) - mu * mu;
        st[bc * 2] = mu; st[bc * 2 + 1] = rsqrtf(var + 1e-5f);
    }
}

// ---------------- instance-norm apply + leaky relu, in place ----------------
__global__ void kiapply(float* __restrict__ f, const float* __restrict__ st,
                        const float* __restrict__ g, const float* __restrict__ b) {
    size_t i = (size_t)blockIdx.x * 256 + threadIdx.x;
    int bc = (int)(i >> 12);
    int c  = bc & 127;
    float v = f[i];
    v = (v - st[bc * 2]) * st[bc * 2 + 1] * g[c] + b[c];
    f[i] = v >= 0.f ? v : 0.01f * v;
}

// ---------------- launch ----------------
extern "C" void kernel_launch(void* const* d_in, const int* in_sizes, int n_in,
                              void* d_out, int out_size) {
    const float* x          = (const float*)d_in[0];
    const float* proj_in_w  = (const float*)d_in[1];
    const float* proj_in_b  = (const float*)d_in[2];
    const float* in_proj_w  = (const float*)d_in[3];
    const float* conv1d_w   = (const float*)d_in[4];
    const float* conv1d_b   = (const float*)d_in[5];
    const float* x_proj_w   = (const float*)d_in[6];
    const float* dt_proj_w  = (const float*)d_in[7];
    const float* dt_proj_b  = (const float*)d_in[8];
    const float* A_log      = (const float*)d_in[9];
    const float* Dv         = (const float*)d_in[10];
    const float* out_proj_w = (const float*)d_in[11];
    const float* proj_out_w = (const float*)d_in[12];
    const float* proj_out_b = (const float*)d_in[13];
    const float* ln_g       = (const float*)d_in[14];
    const float* ln_b       = (const float*)d_in[15];
    const float* in_g       = (const float*)d_in[16];
    const float* in_b       = (const float*)d_in[17];
    const float* conv2d_w   = (const float*)d_in[18];
    const float* conv2d_b   = (const float*)d_in[19];

    float *tin, *t0, *xz, *xs, *dbl, *dt, *y, *t1, *t2, *f, *st;
    cudaGetSymbolAddress((void**)&tin, g_tin);
    cudaGetSymbolAddress((void**)&t0,  g_t0);
    cudaGetSymbolAddress((void**)&xz,  g_xz);
    cudaGetSymbolAddress((void**)&xs,  g_xs);
    cudaGetSymbolAddress((void**)&dbl, g_dbl);
    cudaGetSymbolAddress((void**)&dt,  g_dt);
    cudaGetSymbolAddress((void**)&y,   g_y);
    cudaGetSymbolAddress((void**)&t1,  g_t1);
    cudaGetSymbolAddress((void**)&t2,  g_t2);
    cudaGetSymbolAddress((void**)&f,   g_f);
    cudaGetSymbolAddress((void**)&st,  g_st);

    dim3 tb(32, 8);
    // 1) x (B,64,L) -> tin (B*L,64)
    ktranspose<<<dim3(128, 2, 8), tb>>>(x, tin, 64, 4096);
    // 2) t0 = silu(tin @ proj_in_w^T + b)   (BL,128)
    kgemm<1, 0, 0><<<dim3(2, 256), 256>>>(tin, proj_in_w, proj_in_b, t0,
                                          BL, 128, 64, 64, 128);
    // 3) xz = t0 @ in_proj_w^T              (BL,512)
    kgemm<0, 0, 0><<<dim3(8, 256), 256>>>(t0, in_proj_w, nullptr, xz,
                                          BL, 512, 128, 128, 512);
    // 4) xs = silu(causal conv1d(xm))       (BL,256)
    kconv1d<<<BL, 256>>>(xz, conv1d_w, conv1d_b, xs);
    // 5) dbl = xs @ x_proj_w^T              (BL,136)
    kgemm<0, 0, 0><<<dim3(3, 256), 256>>>(xs, x_proj_w, nullptr, dbl,
                                          BL, 136, 256, 256, 136);
    // 6) dt = softplus(dbl[:,:8] @ dt_proj_w^T + b)  (BL,256)
    kdt<<<BL, 256>>>(dbl, dt_proj_w, dt_proj_b, dt);
    // 7) selective scan + residual D + silu(z) gate  (BL,256)
    kscan<<<256, 256>>>(dt, xs, dbl, xz, A_log, Dv, y);
    // 8) t1 = y @ out_proj_w^T              (BL,128)
    kgemm<0, 0, 0><<<dim3(2, 256), 256>>>(y, out_proj_w, nullptr, t1,
                                          BL, 128, 256, 256, 128);
    // 9) t2 = t1 @ proj_out_w^T + b         (BL,128)
    kgemm<0, 0, 0><<<dim3(2, 256), 256>>>(t1, proj_out_w, proj_out_b, t2,
                                          BL, 128, 128, 128, 128);
    // 10) LayerNorm over 128, in place
    kln<<<BL, 128>>>(t2, ln_g, ln_b);
    // 11) t2 (B,L,128) -> f (B,128,L)
    ktranspose<<<dim3(4, 128, 8), tb>>>(t2, f, 4096, 128);
    // 12-13) instance norm + leaky relu, in place
    kistats<<<1024, 256>>>(f, st);
    kiapply<<<16384, 256>>>(f, st, in_g, in_b);
    // 14) conv2d 3x3 SAME as implicit GEMM (K=1152) + bias -> d_out (NCHW)
    kgemm<0, 1, 1><<<dim3(2, 256), 256>>>(f, conv2d_w, conv2d_b, (float*)d_out,
                                          BL, 128, 1152, 0, 0);
}